// round 11
// baseline (speedup 1.0000x reference)
#include <cuda_runtime.h>

// ---------------------------------------------------------------------------
// SupernodeEncoder, bucket spatial hash, two kernels.
//   K1: scatter (pos,fun0)+(fun1..4) into fixed-capacity cell buckets
//   K2: ONE WARPGROUP (128 thr) PER SUPERNODE: 27-cell query via smem segment
//       table + independent binary search (no loop-carried deps), smem-atomic
//       accumulation (matches are rare), fused [8]->[C] projection.
//       Last-block-out ticket re-zeroes counts (no spinning anywhere).
// ---------------------------------------------------------------------------

#define RADIUS2  0.0025f
#define GRID_DIM 20
#define NC       8000          // 20^3 cells
#define CAP      32            // max pts/cell (lambda = 6.25)
#define QTHR     256           // K2 threads/block = 2 supernode groups
#define GPB      2             // groups per block

// __device__ globals (zero-initialized at module load)
__device__ int    g_count[NC];
__device__ float4 g_b0[NC * CAP];      // x, y, z, fun0
__device__ float4 g_b1[NC * CAP];      // fun1..fun4
__device__ int    g_done;              // K2 completion ticket

__device__ __forceinline__ int cell_coord(float v) {
    int c = (int)(v * (float)GRID_DIM);
    return min(GRID_DIM - 1, max(0, c));
}

// ---------------------------------------------------------------------------
// K1: bucket scatter. Requires g_count == 0 at entry (module-load zero first
// call; K2's tail resets every call).
// ---------------------------------------------------------------------------
__global__ void scatter_kernel(const float* __restrict__ pos,
                               const float* __restrict__ fun, int N) {
    int i = blockIdx.x * blockDim.x + threadIdx.x;
    if (i >= N) return;
    float px = pos[3 * i + 0];
    float py = pos[3 * i + 1];
    float pz = pos[3 * i + 2];
    int cell = (cell_coord(pz) * GRID_DIM + cell_coord(py)) * GRID_DIM
             + cell_coord(px);
    int slot = atomicAdd(&g_count[cell], 1);
    if (slot < CAP) {
        const float* f = fun + (size_t)i * 5;
        int j = (cell << 5) + slot;    // cell * CAP
        g_b0[j] = make_float4(px, py, pz, f[0]);
        g_b1[j] = make_float4(f[1], f[2], f[3], f[4]);
    }
}

// ---------------------------------------------------------------------------
// K2: one 128-thread group per supernode.
// ---------------------------------------------------------------------------
__global__ void __launch_bounds__(QTHR)
query_kernel(const float* __restrict__ pos,
             const int* __restrict__ sidx,
             const float* __restrict__ W,
             const float* __restrict__ b,
             float* __restrict__ out, int M, int C) {
    const int tid    = threadIdx.x;
    const int grp    = tid >> 7;               // 0 or 1
    const int gt     = tid & 127;              // thread within group
    const int lane   = tid & 31;
    const int wwid   = tid >> 5;               // warp within block (0..7)
    const int m      = blockIdx.x * GPB + grp; // supernode id
    const unsigned FULL = 0xffffffffu;

    __shared__ int   s_off [GPB][28];          // exclusive prefix + sentinel
    __shared__ int   s_base[GPB][27];          // bucket base addresses
    __shared__ float s_acc [GPB][9];           // sums(pos3,fun5) + count

    // zero accumulators
    if (tid < GPB * 9) ((float*)s_acc)[tid] = 0.f;

    float sx = 0.f, sy = 0.f, sz = 0.f;
    bool valid = (m < M);
    if (valid) {
        const int s = sidx[m];
        sx = pos[3 * s + 0];
        sy = pos[3 * s + 1];
        sz = pos[3 * s + 2];
    }

    // warp 0 of each group (wwid 0 / wwid 4) builds the segment table
    if ((wwid & 3) == 0) {
        int len = 0, cbase = 0;
        if (valid && lane < 27) {
            int cx = cell_coord(sx), cy = cell_coord(sy), cz = cell_coord(sz);
            int dz = lane / 9 - 1;
            int dy = (lane / 3) % 3 - 1;
            int dx = lane % 3 - 1;
            int z = cz + dz, y = cy + dy, x = cx + dx;
            if ((unsigned)z < GRID_DIM && (unsigned)y < GRID_DIM &&
                (unsigned)x < GRID_DIM) {
                int cell = (z * GRID_DIM + y) * GRID_DIM + x;
                len = min(g_count[cell], CAP);
                cbase = cell << 5;             // cell * CAP
            }
        }
        // warp-convergent inclusive prefix over 27 lengths
        int pre = len;
#pragma unroll
        for (int o = 1; o < 32; o <<= 1) {
            int u = __shfl_up_sync(FULL, pre, o);
            if (lane >= o) pre += u;
        }
        if (lane < 27) {
            s_off [grp][lane] = pre - len;
            s_base[grp][lane] = cbase;
        }
        if (lane == 26) s_off[grp][27] = pre;  // total T (sentinel)
    }
    __syncthreads();

    const int T = s_off[grp][27];

    // candidate loop: ~2 iterations per thread, fully independent (binary
    // search over smem offsets per candidate; no loop-carried state).
    for (int t = gt; t < T; t += 128) {
        int sq = 0;
#pragma unroll
        for (int step = 16; step; step >>= 1) {
            int cand = sq + step;
            if (cand <= 26 && t >= s_off[grp][cand]) sq = cand;
        }
        int j = s_base[grp][sq] + (t - s_off[grp][sq]);
        float4 p0 = g_b0[j];
        float ddx = p0.x - sx;
        float ddy = p0.y - sy;
        float ddz = p0.z - sz;
        float d2 = fmaf(ddx, ddx, fmaf(ddy, ddy, ddz * ddz));
        if (d2 <= RADIUS2) {                   // rare (~26 per group total)
            float4 p1 = g_b1[j];
            float* a = s_acc[grp];
            atomicAdd(a + 0, p0.x);
            atomicAdd(a + 1, p0.y);
            atomicAdd(a + 2, p0.z);
            atomicAdd(a + 3, p0.w);
            atomicAdd(a + 4, p1.x);
            atomicAdd(a + 5, p1.y);
            atomicAdd(a + 6, p1.z);
            atomicAdd(a + 7, p1.w);
            atomicAdd(a + 8, 1.f);
        }
    }
    __syncthreads();

    // projection: each thread handles 2 channels (C == 256, 128 threads)
    if (valid) {
        const float cnt = s_acc[grp][8];
        const bool nonempty = (cnt > 0.5f);
        const float inv = nonempty ? (1.f / cnt) : 0.f;
        float mean[8];
#pragma unroll
        for (int k = 0; k < 8; k++) mean[k] = s_acc[grp][k] * inv;

        if (C == 256) {
            const int c0 = gt * 2;
            const float4* w4 = (const float4*)(W + (size_t)c0 * 8);
            float2 o2;
#pragma unroll
            for (int j = 0; j < 2; j++) {
                float4 wa = w4[2 * j];
                float4 wb = w4[2 * j + 1];
                float acc = b[c0 + j];
                acc = fmaf(mean[0], wa.x, acc);
                acc = fmaf(mean[1], wa.y, acc);
                acc = fmaf(mean[2], wa.z, acc);
                acc = fmaf(mean[3], wa.w, acc);
                acc = fmaf(mean[4], wb.x, acc);
                acc = fmaf(mean[5], wb.y, acc);
                acc = fmaf(mean[6], wb.z, acc);
                acc = fmaf(mean[7], wb.w, acc);
                (&o2.x)[j] = nonempty ? acc : 0.f;
            }
            *(float2*)(out + (size_t)m * 256 + c0) = o2;
        } else {
            for (int c = gt; c < C; c += 128) {
                const float* w = W + (size_t)c * 8;
                float acc = b[c];
#pragma unroll
                for (int k = 0; k < 8; k++) acc = fmaf(mean[k], w[k], acc);
                out[(size_t)m * C + c] = nonempty ? acc : 0.f;
            }
        }
    }

    // ---- last-block-out cleanup (atomic ticket; nobody spins) -------------
    __shared__ int s_last;
    __syncthreads();                   // this block's g_count reads are done
    if (tid == 0) {
        __threadfence();
        s_last = (atomicAdd(&g_done, 1) == (int)gridDim.x - 1) ? 1 : 0;
    }
    __syncthreads();
    if (s_last) {
        for (int i = tid; i < NC; i += QTHR) g_count[i] = 0;
        if (tid == 0) g_done = 0;      // ready for the next replay
    }
}

// ---------------------------------------------------------------------------
extern "C" void kernel_launch(void* const* d_in, const int* in_sizes, int n_in,
                              void* d_out, int out_size) {
    const float* pos  = (const float*)d_in[0];
    const float* fun  = (const float*)d_in[1];
    const int*   sidx = (const int*)d_in[2];
    const float* W    = (const float*)d_in[3];
    const float* b    = (const float*)d_in[4];
    float* out = (float*)d_out;

    const int N = in_sizes[0] / 3;
    const int M = in_sizes[2];
    const int C = in_sizes[4];

    scatter_kernel<<<(N + 255) / 256, 256>>>(pos, fun, N);
    query_kernel<<<(M + GPB - 1) / GPB, QTHR>>>(pos, sidx, W, b, out, M, C);
}

// round 12
// speedup vs baseline: 1.0633x; 1.0633x over previous
#include <cuda_runtime.h>

// ---------------------------------------------------------------------------
// SupernodeEncoder, POINT-CENTRIC formulation (50K-wide parallelism):
//   K1: bucket the 1024 supernodes into a 10^3 grid (cell = 2R) + zero g_acc
//   K2: each point checks its 8-cell neighborhood (~8 supernode candidates),
//       on match fires 9 global float reductions into g_acc[m]
//   K3: per-supernode mean + fused [8]->[C] projection; resets supernode
//       counts after use so every graph replay starts clean.
// ---------------------------------------------------------------------------

#define RADIUS2  0.0025f       // 0.05^2
#define H_INV    10.0f         // 1 / (2R)
#define GD_S     10            // supernode-grid cells per axis
#define NCS      1000          // 10^3
#define CAP_S    32            // max supernodes per cell (lambda ~ 1)
#define MMAX     4096

// __device__ globals (zero-initialized at module load)
__device__ int    s_count[NCS];
__device__ float4 s_bkt[NCS * CAP_S];  // sx, sy, sz, bits(m)
__device__ float  g_acc[MMAX * 9];     // [M][9]: sum(pos3,fun5), count

__device__ __forceinline__ int cc10(float v) {
    int c = (int)(v * H_INV);
    return min(GD_S - 1, max(0, c));
}

// ---------------------------------------------------------------------------
// K1: insert supernodes into buckets + zero g_acc.
// Requires s_count == 0 at entry (module-load zero first call; K3 resets).
// ---------------------------------------------------------------------------
__global__ void build_kernel(const float* __restrict__ pos,
                             const int* __restrict__ sidx, int M) {
    const int t = blockIdx.x * blockDim.x + threadIdx.x;
    const int nt = gridDim.x * blockDim.x;
    for (int i = t; i < M * 9; i += nt) g_acc[i] = 0.f;
    if (t < M) {
        int s = sidx[t];
        float sx = pos[3 * s + 0];
        float sy = pos[3 * s + 1];
        float sz = pos[3 * s + 2];
        int cell = (cc10(sz) * GD_S + cc10(sy)) * GD_S + cc10(sx);
        int slot = atomicAdd(&s_count[cell], 1);
        if (slot < CAP_S)
            s_bkt[(cell << 5) + slot] = make_float4(sx, sy, sz,
                                                    __int_as_float(t));
    }
}

// ---------------------------------------------------------------------------
// K2: point-centric match + reduction. One thread per point.
// ---------------------------------------------------------------------------
__global__ void __launch_bounds__(256)
point_kernel(const float* __restrict__ pos,
             const float* __restrict__ fun, int N) {
    const int i = blockIdx.x * blockDim.x + threadIdx.x;
    if (i >= N) return;

    const float px = pos[3 * i + 0];
    const float py = pos[3 * i + 1];
    const float pz = pos[3 * i + 2];

    const int cx = cc10(px), cy = cc10(py), cz = cc10(pz);
    // octant direction: the only neighbor that can hold a supernode within R
    const int dx = (px > (cx + 0.5f) * 0.1f) ? 1 : -1;
    const int dy = (py > (cy + 0.5f) * 0.1f) ? 1 : -1;
    const int dz = (pz > (cz + 0.5f) * 0.1f) ? 1 : -1;

    // 8 candidate cells (out-of-range -> -1); count loads are independent
    int cells[8];
#pragma unroll
    for (int k = 0; k < 8; k++) {
        int x = cx + ((k & 1)      ? dx : 0);
        int y = cy + (((k >> 1) & 1) ? dy : 0);
        int z = cz + ((k >> 2)     ? dz : 0);
        bool ok = ((unsigned)x < GD_S) & ((unsigned)y < GD_S) &
                  ((unsigned)z < GD_S);
        cells[k] = ok ? ((z * GD_S + y) * GD_S + x) : -1;
    }
    int cnts[8];
#pragma unroll
    for (int k = 0; k < 8; k++)
        cnts[k] = (cells[k] >= 0) ? s_count[cells[k]] : 0;

    bool floaded = false;
    float f0 = 0.f, f1 = 0.f, f2 = 0.f, f3 = 0.f, f4 = 0.f;

#pragma unroll
    for (int k = 0; k < 8; k++) {
        int cn = min(cnts[k], CAP_S);
        int base = cells[k] << 5;
        for (int q = 0; q < cn; q++) {
            float4 e = s_bkt[base + q];
            float ddx = e.x - px;
            float ddy = e.y - py;
            float ddz = e.z - pz;
            float d2 = fmaf(ddx, ddx, fmaf(ddy, ddy, ddz * ddz));
            if (d2 <= RADIUS2) {
                if (!floaded) {
                    const float* f = fun + (size_t)i * 5;
                    f0 = f[0]; f1 = f[1]; f2 = f[2]; f3 = f[3]; f4 = f[4];
                    floaded = true;
                }
                float* a = g_acc + 9 * __float_as_int(e.w);
                atomicAdd(a + 0, px);
                atomicAdd(a + 1, py);
                atomicAdd(a + 2, pz);
                atomicAdd(a + 3, f0);
                atomicAdd(a + 4, f1);
                atomicAdd(a + 5, f2);
                atomicAdd(a + 6, f3);
                atomicAdd(a + 7, f4);
                atomicAdd(a + 8, 1.f);
            }
        }
    }
}

// ---------------------------------------------------------------------------
// K3: projection (one block per supernode) + supernode-count reset.
// ---------------------------------------------------------------------------
__global__ void __launch_bounds__(256)
proj_kernel(const float* __restrict__ W,
            const float* __restrict__ b,
            float* __restrict__ out, int M, int C) {
    const int m = blockIdx.x;
    const int tid = threadIdx.x;

    __shared__ float a[9];
    if (tid < 9) a[tid] = g_acc[m * 9 + tid];
    __syncthreads();

    const float cnt = a[8];
    const bool nonempty = (cnt > 0.5f);
    const float inv = nonempty ? (1.f / cnt) : 0.f;
    float mean[8];
#pragma unroll
    for (int k = 0; k < 8; k++) mean[k] = a[k] * inv;

    for (int c = tid; c < C; c += 256) {
        const float4* w4 = (const float4*)(W + (size_t)c * 8);
        float4 wa = w4[0];
        float4 wb = w4[1];
        float acc = b[c];
        acc = fmaf(mean[0], wa.x, acc);
        acc = fmaf(mean[1], wa.y, acc);
        acc = fmaf(mean[2], wa.z, acc);
        acc = fmaf(mean[3], wa.w, acc);
        acc = fmaf(mean[4], wb.x, acc);
        acc = fmaf(mean[5], wb.y, acc);
        acc = fmaf(mean[6], wb.z, acc);
        acc = fmaf(mean[7], wb.w, acc);
        out[(size_t)m * C + c] = nonempty ? acc : 0.f;
    }

    // block 0 resets the supernode-grid counts for the next replay
    // (runs after K2 is complete; nobody reads s_count in K3)
    if (m == 0) {
        for (int i = tid; i < NCS; i += 256) s_count[i] = 0;
    }
}

// ---------------------------------------------------------------------------
extern "C" void kernel_launch(void* const* d_in, const int* in_sizes, int n_in,
                              void* d_out, int out_size) {
    const float* pos  = (const float*)d_in[0];
    const float* fun  = (const float*)d_in[1];
    const int*   sidx = (const int*)d_in[2];
    const float* W    = (const float*)d_in[3];
    const float* b    = (const float*)d_in[4];
    float* out = (float*)d_out;

    const int N = in_sizes[0] / 3;
    const int M = in_sizes[2];
    const int C = in_sizes[4];

    build_kernel<<<(M + 255) / 256, 256>>>(pos, sidx, M);
    point_kernel<<<(N + 255) / 256, 256>>>(pos, fun, N);
    proj_kernel<<<M, 256>>>(W, b, out, M, C);
}

// round 13
// speedup vs baseline: 1.3196x; 1.2411x over previous
#include <cuda_runtime.h>

// ---------------------------------------------------------------------------
// SupernodeEncoder, point-centric with PER-BLOCK SMEM supernode structure.
//   K_A: every block builds a compact CSR of all M supernodes over a 10^3
//        grid (cell = 2R) in SHARED memory (~1024 gathers, parallel), then
//        streams its slice of points: 8-cell octant lookup in smem, rare
//        matches fire 9 global float reductions into g_acc[m].
//   K_B: per-supernode mean + fused [8]->[C] projection; each block re-zeroes
//        the g_acc entries it consumed (graph-replay invariant; first call
//        relies on module-load zero-init).
// ---------------------------------------------------------------------------

#define RADIUS2  0.0025f       // 0.05^2
#define H_INV    10.0f         // 1 / (2R)
#define GD_S     10            // supernode-grid cells per axis
#define NCS      1000          // 10^3
#define MMAX_SM  2048          // max supernodes held in smem CSR
#define MMAX     4096
#define NTHR     256
#define NBLK_A   296           // 2 CTAs/SM

// __device__ globals (zero-initialized at module load)
__device__ float g_acc[MMAX * 9];      // [M][9]: sum(pos3,fun5), count

__device__ __forceinline__ int cc10(float v) {
    int c = (int)(v * H_INV);
    return min(GD_S - 1, max(0, c));
}

// ---------------------------------------------------------------------------
// K_A: per-block smem CSR build + point-centric match.
// ---------------------------------------------------------------------------
__global__ void __launch_bounds__(NTHR)
match_kernel(const float* __restrict__ pos,
             const float* __restrict__ fun,
             const int* __restrict__ sidx,
             int N, int M) {
    __shared__ int    s_cnt  [NCS];    // per-cell supernode count
    __shared__ int    s_start[NCS];    // per-cell CSR start
    __shared__ int    s_psum [NTHR];   // scan workspace
    __shared__ float4 s_sp   [MMAX_SM];// packed supernodes (x,y,z,bits(m))

    const int tid  = threadIdx.x;
    const int gtid = blockIdx.x * NTHR + tid;
    const int stride = NBLK_A * NTHR;

    // ---- build: histogram ----
    for (int i = tid; i < NCS; i += NTHR) s_cnt[i] = 0;
    __syncthreads();

    int   mycell[8], myslot[8];
    float4 myval[8];
    int nrec = 0;
    for (int j = tid; j < M && nrec < 8; j += NTHR) {
        int s = sidx[j];
        float sx = pos[3 * s + 0];
        float sy = pos[3 * s + 1];
        float sz = pos[3 * s + 2];
        int cell = (cc10(sz) * GD_S + cc10(sy)) * GD_S + cc10(sx);
        mycell[nrec] = cell;
        myslot[nrec] = atomicAdd(&s_cnt[cell], 1);
        myval [nrec] = make_float4(sx, sy, sz, __int_as_float(j));
        nrec++;
    }
    __syncthreads();

    // ---- build: block scan over NCS cell counts (4 cells / thread) ----
    int loc[4], tot = 0;
#pragma unroll
    for (int q = 0; q < 4; q++) {
        int idx = tid * 4 + q;
        int v = (idx < NCS) ? s_cnt[idx] : 0;
        loc[q] = tot;
        tot += v;
    }
    s_psum[tid] = tot;
    __syncthreads();
    for (int o = 1; o < NTHR; o <<= 1) {
        int u = (tid >= o) ? s_psum[tid - o] : 0;
        __syncthreads();
        s_psum[tid] += u;
        __syncthreads();
    }
    int ex = s_psum[tid] - tot;
#pragma unroll
    for (int q = 0; q < 4; q++) {
        int idx = tid * 4 + q;
        if (idx < NCS) s_start[idx] = ex + loc[q];
    }
    __syncthreads();

    // ---- build: scatter supernodes into CSR slots ----
    for (int r = 0; r < nrec; r++) {
        int slot = s_start[mycell[r]] + myslot[r];
        if (slot < MMAX_SM) s_sp[slot] = myval[r];
    }
    __syncthreads();

    // ---- match: stream this block's slice of points ----
    for (int i = gtid; i < N; i += stride) {
        float px = pos[3 * i + 0];
        float py = pos[3 * i + 1];
        float pz = pos[3 * i + 2];

        int cx = cc10(px), cy = cc10(py), cz = cc10(pz);
        int dx = (px > (cx + 0.5f) * 0.1f) ? 1 : -1;
        int dy = (py > (cy + 0.5f) * 0.1f) ? 1 : -1;
        int dz = (pz > (cz + 0.5f) * 0.1f) ? 1 : -1;

        bool floaded = false;
        float f0 = 0.f, f1 = 0.f, f2 = 0.f, f3 = 0.f, f4 = 0.f;

#pragma unroll
        for (int k = 0; k < 8; k++) {
            int x = cx + ((k & 1)        ? dx : 0);
            int y = cy + (((k >> 1) & 1) ? dy : 0);
            int z = cz + ((k >> 2)       ? dz : 0);
            if (((unsigned)x >= GD_S) | ((unsigned)y >= GD_S) |
                ((unsigned)z >= GD_S)) continue;
            int cell = (z * GD_S + y) * GD_S + x;
            int beg = s_start[cell];
            int end = beg + s_cnt[cell];
            for (int q = beg; q < end; q++) {
                float4 e = s_sp[q];
                float ddx = e.x - px;
                float ddy = e.y - py;
                float ddz = e.z - pz;
                float d2 = fmaf(ddx, ddx, fmaf(ddy, ddy, ddz * ddz));
                if (d2 <= RADIUS2) {            // rare: ~0.55 per point
                    if (!floaded) {
                        const float* f = fun + (size_t)i * 5;
                        f0 = f[0]; f1 = f[1]; f2 = f[2]; f3 = f[3]; f4 = f[4];
                        floaded = true;
                    }
                    float* a = g_acc + 9 * __float_as_int(e.w);
                    atomicAdd(a + 0, px);
                    atomicAdd(a + 1, py);
                    atomicAdd(a + 2, pz);
                    atomicAdd(a + 3, f0);
                    atomicAdd(a + 4, f1);
                    atomicAdd(a + 5, f2);
                    atomicAdd(a + 6, f3);
                    atomicAdd(a + 7, f4);
                    atomicAdd(a + 8, 1.f);
                }
            }
        }
    }
}

// ---------------------------------------------------------------------------
// K_B: projection (one block per supernode) + g_acc reset for next replay.
// ---------------------------------------------------------------------------
__global__ void __launch_bounds__(NTHR)
proj_kernel(const float* __restrict__ W,
            const float* __restrict__ b,
            float* __restrict__ out, int C) {
    const int m = blockIdx.x;
    const int tid = threadIdx.x;

    __shared__ float a[9];
    if (tid < 9) a[tid] = g_acc[m * 9 + tid];
    __syncthreads();

    const float cnt = a[8];
    const bool nonempty = (cnt > 0.5f);
    const float inv = nonempty ? (1.f / cnt) : 0.f;
    float mean[8];
#pragma unroll
    for (int k = 0; k < 8; k++) mean[k] = a[k] * inv;

    for (int c = tid; c < C; c += NTHR) {
        const float4* w4 = (const float4*)(W + (size_t)c * 8);
        float4 wa = w4[0];
        float4 wb = w4[1];
        float acc = b[c];
        acc = fmaf(mean[0], wa.x, acc);
        acc = fmaf(mean[1], wa.y, acc);
        acc = fmaf(mean[2], wa.z, acc);
        acc = fmaf(mean[3], wa.w, acc);
        acc = fmaf(mean[4], wb.x, acc);
        acc = fmaf(mean[5], wb.y, acc);
        acc = fmaf(mean[6], wb.z, acc);
        acc = fmaf(mean[7], wb.w, acc);
        out[(size_t)m * C + c] = nonempty ? acc : 0.f;
    }

    // reset the accumulators this block consumed (replay-invariant)
    __syncthreads();
    if (tid < 9) g_acc[m * 9 + tid] = 0.f;
}

// ---------------------------------------------------------------------------
extern "C" void kernel_launch(void* const* d_in, const int* in_sizes, int n_in,
                              void* d_out, int out_size) {
    const float* pos  = (const float*)d_in[0];
    const float* fun  = (const float*)d_in[1];
    const int*   sidx = (const int*)d_in[2];
    const float* W    = (const float*)d_in[3];
    const float* b    = (const float*)d_in[4];
    float* out = (float*)d_out;

    const int N = in_sizes[0] / 3;
    const int M = in_sizes[2];
    const int C = in_sizes[4];

    match_kernel<<<NBLK_A, NTHR>>>(pos, fun, sidx, N, M);
    proj_kernel<<<M, NTHR>>>(W, b, out, C);
}